// round 8
// baseline (speedup 1.0000x reference)
#include <cuda_runtime.h>
#include <math.h>

#define NN   262144
#define DIMM 256
#define NH   4
#define HD   64
#define BSEG 4096
#define SCALE 0.125f
#define EPSV 1e-8f
#define RG   3      // k_main ring slots per warp (slot = 4 rows = 4KB)

// ---- device scratch ----
__device__ float g_wtil[NH * DIMM];
__device__ float g_ctil[NH];
__device__ int   g_segstart[BSEG + 1];
__device__ float g_t[BSEG * NH * DIMM];  // normalized weighted sums t~
__device__ float g_coef[BSEG * NH];      // esum/(esum+eps)

// ---- packed f32x2 helpers ----
__device__ __forceinline__ unsigned long long f2mul(unsigned long long a, unsigned long long b) {
    unsigned long long r; asm("mul.rn.f32x2 %0,%1,%2;" : "=l"(r) : "l"(a), "l"(b)); return r;
}
__device__ __forceinline__ unsigned long long f2fma(unsigned long long a, unsigned long long b,
                                                    unsigned long long c) {
    unsigned long long r; asm("fma.rn.f32x2 %0,%1,%2,%3;" : "=l"(r) : "l"(a), "l"(b), "l"(c)); return r;
}
__device__ __forceinline__ unsigned long long fpack(float a, float b) {
    unsigned long long r; asm("mov.b64 %0,{%1,%2};" : "=l"(r) : "f"(a), "f"(b)); return r;
}
__device__ __forceinline__ float f2lo(unsigned long long a) { float2 p = *(float2*)&a; return p.x; }
__device__ __forceinline__ float f2hi(unsigned long long a) { float2 p = *(float2*)&a; return p.y; }

__device__ __forceinline__ void cpa16(void* dst_smem, const void* src) {
    unsigned u = (unsigned)__cvta_generic_to_shared(dst_smem);
    asm volatile("cp.async.cg.shared.global [%0], [%1], 16;" :: "r"(u), "l"(src) : "memory");
}
#define CP_COMMIT() asm volatile("cp.async.commit_group;" ::: "memory")
#define CP_WAIT(n)  asm volatile("cp.async.wait_group %0;" :: "n"(n) : "memory")

// ---------------------------------------------------------------------------
__global__ void k_fold(const float* __restrict__ q,
                       const float* __restrict__ kw,
                       const float* __restrict__ kb) {
    int h = blockIdx.x;
    int j = threadIdx.x;
    float acc = 0.f;
#pragma unroll 8
    for (int d = 0; d < HD; d++)
        acc = fmaf(q[h * HD + d], kw[(h * HD + d) * DIMM + j], acc);
    g_wtil[h * DIMM + j] = acc * SCALE;
    if (j == 0) {
        float c = 0.f;
#pragma unroll 8
        for (int d = 0; d < HD; d++)
            c = fmaf(q[h * HD + d], kb[h * HD + d], c);
        g_ctil[h] = c * SCALE;
    }
}

// ---------------------------------------------------------------------------
__global__ void k_seg(const int* __restrict__ batch) {
    int i = blockIdx.x * blockDim.x + threadIdx.x;
    if (i >= NN) return;
    int cur  = batch[i];
    int prev = (i == 0) ? -1 : batch[i - 1];
    for (int b = prev + 1; b <= cur; b++) g_segstart[b] = i;
    if (i == NN - 1)
        for (int b = cur + 1; b <= BSEG; b++) g_segstart[b] = NN;
}

// ---------------------------------------------------------------------------
// k_main: warp per segment, cp.async ring of 4-row groups (RG=3 slots,
// prefetch 2 ahead -> 8KB/warp in flight, 16 warps/SM -> 128KB/SM).
// Per group: 16-item butterfly multi-reduce (16 shfl), ONE exp per lane,
// per-row broadcast + f32x2 accumulation. Item i=(r*4+h) lives at lane 2i.
// Lanes read back only their own cp.async'd 16B chunks -> no barriers.
// ---------------------------------------------------------------------------
__global__ void __launch_bounds__(256, 2) k_main(const float* __restrict__ x) {
    extern __shared__ float4 ring_all[];
    const int lane = threadIdx.x & 31;
    const int wid  = threadIdx.x >> 5;
    const int b    = blockIdx.x * 8 + wid;
    float4* ring = ring_all + wid * (RG * 256);

    const int s0  = g_segstart[b];
    const int s1  = g_segstart[b + 1];
    const int cnt = s1 - s0;
    const int ng  = (cnt + 3) >> 2;

    const float4* wt4 = (const float4*)g_wtil;
    ulonglong2 w0[NH], w1[NH];
#pragma unroll
    for (int h = 0; h < NH; h++) {
        float4 t = wt4[h * 64 + lane];      w0[h] = *(ulonglong2*)&t;
        float4 u = wt4[h * 64 + 32 + lane]; w1[h] = *(ulonglong2*)&u;
    }
    const float ctv = g_ctil[(lane >> 1) & 3];
    const int   r_mine = (lane >> 3) & 3;

    ulonglong2 accA[NH], accB[NH];
#pragma unroll
    for (int h = 0; h < NH; h++) { accA[h].x = accA[h].y = 0ull; accB[h].x = accB[h].y = 0ull; }
    float es = 0.f;

    const float4* xp = (const float4*)x;

#define ISSUE(G) do {                                                   \
        float4* d_ = ring + ((G) % RG) * 256;                           \
        int base_ = s0 + 4 * (G);                                       \
        _Pragma("unroll")                                               \
        for (int rr_ = 0; rr_ < 4; rr_++) {                             \
            int r_ = min(base_ + rr_, s1 - 1);                          \
            cpa16(d_ + rr_ * 64 + lane,      xp + (size_t)r_ * 64 + lane);      \
            cpa16(d_ + rr_ * 64 + 32 + lane, xp + (size_t)r_ * 64 + 32 + lane); \
        } } while (0)

    if (ng > 0) ISSUE(0);
    CP_COMMIT();
    if (ng > 1) ISSUE(1);
    CP_COMMIT();

    for (int g = 0; g < ng; g++) {
        if (g + 2 < ng) ISSUE(g + 2);
        CP_COMMIT();
        CP_WAIT(2);
        const float4* sl = ring + (g % RG) * 256;
        float4 f[8];
#pragma unroll
        for (int rr = 0; rr < 4; rr++) {
            f[2 * rr]     = sl[rr * 64 + lane];
            f[2 * rr + 1] = sl[rr * 64 + 32 + lane];
        }
        // 16 partial dots (this lane's j-slice)
        float a[16];
#pragma unroll
        for (int r = 0; r < 4; r++) {
            ulonglong2 v0 = *(ulonglong2*)&f[2 * r], v1 = *(ulonglong2*)&f[2 * r + 1];
#pragma unroll
            for (int h = 0; h < NH; h++) {
                unsigned long long p;
                p = f2mul(v0.x, w0[h].x); p = f2fma(v0.y, w0[h].y, p);
                p = f2fma(v1.x, w1[h].x, p); p = f2fma(v1.y, w1[h].y, p);
                a[r * 4 + h] = f2lo(p) + f2hi(p);
            }
        }
        // 16-item butterfly: item i ends complete at lanes {2i, 2i+1}
        {
            const bool t4b = (lane & 16) != 0;
#pragma unroll
            for (int i = 0; i < 8; i++) {
                float mine = t4b ? a[i + 8] : a[i];
                float oth  = t4b ? a[i]     : a[i + 8];
                oth = __shfl_xor_sync(0xffffffffu, oth, 16);
                a[i] = mine + oth;
            }
            const bool t3b = (lane & 8) != 0;
#pragma unroll
            for (int i = 0; i < 4; i++) {
                float mine = t3b ? a[i + 4] : a[i];
                float oth  = t3b ? a[i]     : a[i + 4];
                oth = __shfl_xor_sync(0xffffffffu, oth, 8);
                a[i] = mine + oth;
            }
            const bool t2b = (lane & 4) != 0;
#pragma unroll
            for (int i = 0; i < 2; i++) {
                float mine = t2b ? a[i + 2] : a[i];
                float oth  = t2b ? a[i]     : a[i + 2];
                oth = __shfl_xor_sync(0xffffffffu, oth, 4);
                a[i] = mine + oth;
            }
            const bool t1b = (lane & 2) != 0;
            float mine = t1b ? a[1] : a[0];
            float oth  = t1b ? a[0] : a[1];
            oth = __shfl_xor_sync(0xffffffffu, oth, 2);
            a[0] = mine + oth;
            a[0] += __shfl_xor_sync(0xffffffffu, a[0], 1);
        }
        // ONE exp per lane for its item (r_mine, h=(lane>>1)&3)
        bool valid = (4 * g + r_mine) < cnt;
        float e = valid ? __expf(a[0] + ctv) : 0.f;
        if (!(lane & 1)) es += e;

        // per-row: broadcast 4 e's (item r*4+h at lane 8r+2h) and accumulate
#pragma unroll
        for (int r = 0; r < 4; r++) {
            float e0 = __shfl_sync(0xffffffffu, e, 8 * r + 0);
            float e1 = __shfl_sync(0xffffffffu, e, 8 * r + 2);
            float e2 = __shfl_sync(0xffffffffu, e, 8 * r + 4);
            float e3 = __shfl_sync(0xffffffffu, e, 8 * r + 6);
            ulonglong2 v0 = *(ulonglong2*)&f[2 * r], v1 = *(ulonglong2*)&f[2 * r + 1];
            unsigned long long k0 = fpack(e0, e0), k1 = fpack(e1, e1);
            unsigned long long k2 = fpack(e2, e2), k3 = fpack(e3, e3);
            accA[0].x = f2fma(k0, v0.x, accA[0].x); accA[0].y = f2fma(k0, v0.y, accA[0].y);
            accB[0].x = f2fma(k0, v1.x, accB[0].x); accB[0].y = f2fma(k0, v1.y, accB[0].y);
            accA[1].x = f2fma(k1, v0.x, accA[1].x); accA[1].y = f2fma(k1, v0.y, accA[1].y);
            accB[1].x = f2fma(k1, v1.x, accB[1].x); accB[1].y = f2fma(k1, v1.y, accB[1].y);
            accA[2].x = f2fma(k2, v0.x, accA[2].x); accA[2].y = f2fma(k2, v0.y, accA[2].y);
            accB[2].x = f2fma(k2, v1.x, accB[2].x); accB[2].y = f2fma(k2, v1.y, accB[2].y);
            accA[3].x = f2fma(k3, v0.x, accA[3].x); accA[3].y = f2fma(k3, v0.y, accA[3].y);
            accB[3].x = f2fma(k3, v1.x, accB[3].x); accB[3].y = f2fma(k3, v1.y, accB[3].y);
        }
    }
#undef ISSUE

    // esum per head: fold r-partners (xor 8 then 16); esum[h] lands at lane 2h
    es += __shfl_xor_sync(0xffffffffu, es, 8);
    es += __shfl_xor_sync(0xffffffffu, es, 16);
    float es0 = __shfl_sync(0xffffffffu, es, 0);
    float es1 = __shfl_sync(0xffffffffu, es, 2);
    float es2 = __shfl_sync(0xffffffffu, es, 4);
    float es3 = __shfl_sync(0xffffffffu, es, 6);

    float iv0 = 1.0f / (es0 + EPSV), iv1 = 1.0f / (es1 + EPSV);
    float iv2 = 1.0f / (es2 + EPSV), iv3 = 1.0f / (es3 + EPSV);
    unsigned long long ii[NH] = { fpack(iv0, iv0), fpack(iv1, iv1),
                                  fpack(iv2, iv2), fpack(iv3, iv3) };
    float4* tp = (float4*)(g_t + (size_t)b * NH * DIMM);
#pragma unroll
    for (int h = 0; h < NH; h++) {
        ulonglong2 sa, sb;
        sa.x = f2mul(ii[h], accA[h].x); sa.y = f2mul(ii[h], accA[h].y);
        sb.x = f2mul(ii[h], accB[h].x); sb.y = f2mul(ii[h], accB[h].y);
        tp[h * 64 + lane]      = *(float4*)&sa;
        tp[h * 64 + 32 + lane] = *(float4*)&sb;
    }
    if (lane < NH) {
        float cf = (lane == 0) ? es0 * iv0 : (lane == 1) ? es1 * iv1
                 : (lane == 2) ? es2 * iv2 : es3 * iv3;
        g_coef[b * NH + lane] = cf;
    }
}

// ---------------------------------------------------------------------------
// k_out: d-split GEMM. grid = (BSEG/32, NH*2), 128 threads.
// Block handles 32 b x 32 d (half a head's d range). Thread tile 4d x 2b.
// w transposed [j4][d_local] pad-33; t [b][j4] pad-65. All LDS <=8 distinct
// addresses -> 1 wavefront each. 68KB smem -> 3 blocks/SM.
// ---------------------------------------------------------------------------
__global__ void __launch_bounds__(128) k_out(const float* __restrict__ vw,
                                             const float* __restrict__ vb,
                                             float* __restrict__ out) {
    extern __shared__ float sm[];
    ulonglong2* sw2    = (ulonglong2*)sm;                      // [j4][dl] stride 33
    ulonglong2* t4     = (ulonglong2*)(sm + 64 * 33 * 4);      // [b][j4] stride 65
    float*      coef_s = sm + 64 * 33 * 4 + 32 * 65 * 4;

    const int h   = blockIdx.y >> 1;
    const int dh  = blockIdx.y & 1;
    const int b0  = blockIdx.x * 32;
    const int tid = threadIdx.x;
    const int d_base = dh * 32;

    // stage w half-slice transposed (coalesced reads, conflict-free writes)
    {
        const float4* vw4 = (const float4*)(vw + (size_t)(h * 64 + d_base) * DIMM);
#pragma unroll
        for (int s = 0; s < 16; s++) {
            int i = tid + s * 128;        // dl = i>>6 (0..31), c = i&63
            int dl = i >> 6, c = i & 63;
            float4 v = vw4[dl * 64 + c];
            sw2[c * 33 + dl] = *(ulonglong2*)&v;
        }
    }
    // stage t tile (pad-65)
#pragma unroll
    for (int s = 0; s < 16; s++) {
        int i = tid + s * 128;
        int row = i >> 6, c = i & 63;
        t4[row * 65 + c] = ((const ulonglong2*)g_t)[((size_t)(b0 + row) * NH + h) * 64 + c];
    }
    if (tid < 32) coef_s[tid] = g_coef[(b0 + tid) * NH + h];
    __syncthreads();

    const int dq = tid & 7;     // d_local = dq + 8*di, di=0..3
    const int bq = tid >> 3;    // b = b0 + bq + 16*k, k=0..1

    unsigned long long accx[4][2], accy[4][2];
#pragma unroll
    for (int di = 0; di < 4; di++)
#pragma unroll
        for (int k = 0; k < 2; k++) { accx[di][k] = 0ull; accy[di][k] = 0ull; }

#pragma unroll 4
    for (int j4 = 0; j4 < 64; j4++) {
        ulonglong2 w[4], t[2];
#pragma unroll
        for (int di = 0; di < 4; di++) w[di] = sw2[j4 * 33 + dq + 8 * di];
#pragma unroll
        for (int k = 0; k < 2; k++)   t[k]  = t4[(bq + 16 * k) * 65 + j4];
#pragma unroll
        for (int di = 0; di < 4; di++)
#pragma unroll
            for (int k = 0; k < 2; k++) {
                accx[di][k] = f2fma(w[di].x, t[k].x, accx[di][k]);
                accy[di][k] = f2fma(w[di].y, t[k].y, accy[di][k]);
            }
    }

    float bv[4];
#pragma unroll
    for (int di = 0; di < 4; di++) bv[di] = vb[h * 64 + d_base + dq + 8 * di];

#pragma unroll
    for (int k = 0; k < 2; k++) {
        int bb = bq + 16 * k;
        float cf = coef_s[bb];
        float* op = out + (size_t)(b0 + bb) * DIMM + h * 64 + d_base;
#pragma unroll
        for (int di = 0; di < 4; di++) {
            float r = (f2lo(accx[di][k]) + f2hi(accx[di][k]))
                    + (f2lo(accy[di][k]) + f2hi(accy[di][k]));
            op[dq + 8 * di] = fmaf(cf, bv[di], r);
        }
    }
}

// ---------------------------------------------------------------------------
extern "C" void kernel_launch(void* const* d_in, const int* in_sizes, int n_in,
                              void* d_out, int out_size) {
    const float* x     = (const float*)d_in[0];
    const int*   batch = (const int*)d_in[1];
    const float* q     = (const float*)d_in[2];
    const float* kw    = (const float*)d_in[3];
    const float* kb    = (const float*)d_in[4];
    const float* vw    = (const float*)d_in[5];
    const float* vb    = (const float*)d_in[6];
    float*       out   = (float*)d_out;

    const int smem_main = 8 * RG * 256 * 16;                          // 98304
    const int smem_out  = 64 * 33 * 16 + 32 * 65 * 16 + 32 * 4;       // 67200
    cudaFuncSetAttribute(k_main, cudaFuncAttributeMaxDynamicSharedMemorySize, smem_main);
    cudaFuncSetAttribute(k_out,  cudaFuncAttributeMaxDynamicSharedMemorySize, smem_out);

    k_fold<<<NH, 256>>>(q, kw, kb);
    k_seg<<<NN / 256, 256>>>(batch);
    k_main<<<BSEG / 8, 256, smem_main>>>(x);
    k_out<<<dim3(BSEG / 32, NH * 2), 128, smem_out>>>(vw, vb, out);
}